// round 12
// baseline (speedup 1.0000x reference)
#include <cuda_runtime.h>
#include <cstdint>

// LambdaLoss: B=4096 lists, L=128 items.
// loss = mean over valid lists of
//        [ sum_{i,j: rel_i>rel_j} (rel_i-rel_j)*softplus(-(p_i-p_j)) / cnt ]
//
// softplus(-(p_w-p_l)) = ln(1 + e^{p_l}*e^{-p_w}); precompute e_i, rec_i.
// Counting-sort by rel (ascending): winner = higher sorted index -> pair
// orientation is static for 2 of the 4 pair forms per k; the other 2 share
// one index-derived predicate. rd==0 pairs contribute exactly 0.
//
// R12: 2x2 sorted tiling, ONE LIST PER 64-THREAD BLOCK, launch_bounds(64,28)
// -> 28 blocks/SM resident (56 warps, 87.5% ceiling) vs 27.7 supplied:
// exactly one wave, max warp supply to keep the MUFU pipe saturated.
// Thread lj owns sorted items A=lj, B=lj+64. k=1..31: v1=S[lj+k],
// v2=S[lj+64+k] (dup region [128,160) handles wrap) -> 4 pairs; k=32 -> 2;
// {A,B} in-register. 64*127 = 8128 = C(128,2).

#define LL_B   4096
#define LL_L   128
#define LOG2E  1.4426950408889634f
#define LN2    0.6931471805599453f

__device__ float g_sum   = 0.0f;
__device__ int   g_valid = 0;
__device__ int   g_done  = 0;

__device__ __forceinline__ float fast_ex2(float x) {
    float r; asm("ex2.approx.f32 %0, %1;" : "=f"(r) : "f"(x)); return r;
}
__device__ __forceinline__ float fast_lg2(float x) {
    float r; asm("lg2.approx.f32 %0, %1;" : "=f"(r) : "f"(x)); return r;
}

__global__ __launch_bounds__(64, 28) void ll_main_kernel(
    const float* __restrict__ pred,
    const float* __restrict__ rel,
    float* __restrict__ out)
{
    __shared__ float4 S[160];   // sorted (e, rec, rel, _); [128,160) dup of [0,32)
    __shared__ int    hist[8];
    __shared__ int    base[8];
    __shared__ float  wsum[2];

    const int t    = threadIdx.x;     // 0..63 == lj
    const int list = blockIdx.x;

    const float* P = pred + list * LL_L;
    const float* R = rel  + list * LL_L;

    // prologue: each thread handles 2 items
    const float p0 = P[t],       r0 = R[t];
    const float p1 = P[t + 64],  r1 = R[t + 64];
    const int   c0 = (int)r0, c1 = (int)r1;        // rel in {0..4}
    const float q0 = p0 * LOG2E,  q1 = p1 * LOG2E;
    const float e0 = fast_ex2(q0), rc0 = fast_ex2(-q0);
    const float e1 = fast_ex2(q1), rc1 = fast_ex2(-q1);

    if (t < 8) hist[t] = 0;
    __syncthreads();
    atomicAdd(&hist[c0], 1);
    atomicAdd(&hist[c1], 1);
    __syncthreads();
    if (t == 0) {
        int a = 0;
#pragma unroll
        for (int c = 0; c < 5; c++) { base[c] = a; a += hist[c]; }
    }
    __syncthreads();
    {
        const int pos0 = atomicAdd(&base[c0], 1);
        const int pos1 = atomicAdd(&base[c1], 1);
        const float4 u0 = make_float4(e0, rc0, r0, 0.0f);
        const float4 u1 = make_float4(e1, rc1, r1, 0.0f);
        S[pos0] = u0;
        S[pos1] = u1;
        if (pos0 < 32) S[pos0 + 128] = u0;
        if (pos1 < 32) S[pos1 + 128] = u1;
    }
    __syncthreads();

    // self items at sorted positions t and t+64
    const float4 sa = S[t];
    const float4 sb = S[t + 64];
    const float eA = sa.x, cA = sa.y, rA = sa.z;
    const float eB = sb.x, cB = sb.y, rB = sb.z;

    float acc0 = 0.0f, acc1 = 0.0f, acc2 = 0.0f, acc3 = 0.0f;

#pragma unroll
    for (int k = 1; k < 32; k++) {
        const float4 v1 = S[t + k];        // index t+k <= 94: never wraps
        const float4 v2 = S[t + 64 + k];   // wraps (dup) when t+64+k >= 128
        const bool  wr = (t + 64 + k) >= LL_L;

        // {A, t+k}: partner higher sorted index -> partner wins (static)
        acc0 = fmaf(v1.z - rA, fast_lg2(fmaf(eA, v1.y, 1.0f)), acc0);
        // {B, t+k}: t+k < t+64 -> self B wins (static)
        acc1 = fmaf(rB - v1.z, fast_lg2(fmaf(v1.x, cB, 1.0f)), acc1);
        // {A, v2}: no wrap -> partner wins; wrap (idx t+k-64 < t) -> A wins
        {
            float tt = wr ? fmaf(v2.x, cA, 1.0f) : fmaf(eA, v2.y, 1.0f);
            acc2 = fmaf(fabsf(v2.z - rA), fast_lg2(tt), acc2);
        }
        // {B, v2}: same predicate
        {
            float tt = wr ? fmaf(v2.x, cB, 1.0f) : fmaf(eB, v2.y, 1.0f);
            acc3 = fmaf(fabsf(v2.z - rB), fast_lg2(tt), acc3);
        }
    }
    {   // k = 32: pairs {A, t+32} and {B, t+96 (wraps for t>=32)}
        const float4 v1 = S[t + 32];
        acc0 = fmaf(v1.z - rA, fast_lg2(fmaf(eA, v1.y, 1.0f)), acc0);
        const float4 v2 = S[t + 96];
        const bool  wr = (t + 96) >= LL_L;
        float tt = wr ? fmaf(v2.x, cB, 1.0f) : fmaf(eB, v2.y, 1.0f);
        acc1 = fmaf(fabsf(v2.z - rB), fast_lg2(tt), acc1);
    }
    // distance-64 pair {A, B}: B higher sorted index
    acc2 = fmaf(rB - rA, fast_lg2(fmaf(eA, cB, 1.0f)), acc2);

    float acc = (acc0 + acc1) + (acc2 + acc3);

    // warp reduction, then combine the two warps
#pragma unroll
    for (int off = 16; off; off >>= 1)
        acc += __shfl_xor_sync(0xffffffffu, acc, off);
    if ((t & 31) == 0) wsum[t >> 5] = acc;
    __syncthreads();

    if (t == 0) {
        float s = (wsum[0] + wsum[1]) * LN2;
        const int n0 = hist[0], n1 = hist[1], n2 = hist[2];
        const int n3 = hist[3], n4 = hist[4];
        const int cnt = n1 * n0
                      + n2 * (n0 + n1)
                      + n3 * (n0 + n1 + n2)
                      + n4 * (n0 + n1 + n2 + n3);
        if (cnt > 0) {
            atomicAdd(&g_sum, s / (float)cnt);
            atomicAdd(&g_valid, 1);
        }
        __threadfence();
        const int prev = atomicAdd(&g_done, 1);
        if (prev == gridDim.x - 1) {
            const float gs = g_sum;
            const int   gv = g_valid;
            out[0] = (gv > 0) ? (gs / (float)gv) : 0.0f;
            g_sum   = 0.0f;
            g_valid = 0;
            g_done  = 0;
        }
    }
}

extern "C" void kernel_launch(void* const* d_in, const int* in_sizes, int n_in,
                              void* d_out, int out_size)
{
    const float* pred = (const float*)d_in[0];
    const float* rel  = (const float*)d_in[1];
    float* out = (float*)d_out;

    ll_main_kernel<<<LL_B, 64>>>(pred, rel, out);
}